// round 10
// baseline (speedup 1.0000x reference)
#include <cuda_runtime.h>
#include <cuda_bf16.h>
#include <math.h>
#include <cstdint>

#define BB 64
#define CINN 64
#define COUTT 128
#define NPIX 1024
#define TC 4
#define NUNITS 2048

// fused SMEM: Ys[36864 f32] = 147456 B; W (40 rows x 272B) aliases Ys tail at 131072
// (W read only during GEMM; Ys rows 32..35 written only after GEMM sync). red at 147456.
#define SM_W  131072
#define SM_RED 147456
#define SMEM_TOTAL 147584

// A_g: per (b,chunk=16cin) plane of 4096 uint4 in m16n8k8-tf32 fragment order:
// idx = mtile*64 + kk*32 + lane; uint4 = {a0,a1,a2,a3} for px rows mtile*16..+15, k=chunk*16+kk*8..+7
__device__ uint4 A_g[BB * 4 * 4096];
__device__ float g_psum[COUTT * BB];
__device__ float g_psumsq[COUTT * BB];
__device__ float g_scale[COUTT];
__device__ float g_shift[COUTT];

__device__ __forceinline__ void mma_tf32(float* d, const uint32_t* a, const uint32_t* b) {
    asm volatile("mma.sync.aligned.m16n8k8.row.col.f32.tf32.tf32.f32 "
        "{%0,%1,%2,%3}, {%4,%5,%6,%7}, {%8,%9}, {%0,%1,%2,%3};"
        : "+f"(d[0]), "+f"(d[1]), "+f"(d[2]), "+f"(d[3])
        : "r"(a[0]), "r"(a[1]), "r"(a[2]), "r"(a[3]), "r"(b[0]), "r"(b[1]));
}
__device__ __forceinline__ uint32_t to_tf32(float f) {
    uint32_t o;
    asm("cvt.rna.tf32.f32 %0, %1;" : "=r"(o) : "f"(f));
    return o;
}
__device__ __forceinline__ int fd3(int a) { return (a + 24) / 3 - 8; }  // floor(a/3), a>=-24

// ---- prologue: per (chunk,b) emit tf32 A plane in fragment order (verified) ----
__global__ void __launch_bounds__(512) build_A(const float* __restrict__ x)
{
    extern __shared__ float Xs[];   // [16][1032]
    const int tid = threadIdx.x, chunk = blockIdx.x, b = blockIdx.y;
    const float4* xg = (const float4*)(x + (size_t)b * CINN * NPIX + chunk * 16 * NPIX);
#pragma unroll
    for (int j = 0; j < 8; j++) {
        int idx = tid + 512 * j;
        int ci = idx >> 8, px4 = idx & 255;
        *(float4*)(Xs + ci * 1032 + px4 * 4) = xg[idx];
    }
    __syncthreads();
    uint4* pb = A_g + (size_t)(b * 4 + chunk) * 4096;
#pragma unroll
    for (int j = 0; j < 8; j++) {
        int idx = tid + 512 * j;
        int l = idx & 31, t = l & 3, g = l >> 2;
        int kk = (idx >> 5) & 1, mtile = idx >> 6;
        int px = mtile * 16 + g, k = kk * 8 + t;
        uint4 v;
        v.x = to_tf32(Xs[k * 1032 + px]);
        v.y = to_tf32(Xs[k * 1032 + px + 8]);
        v.z = to_tf32(Xs[(k + 4) * 1032 + px]);
        v.w = to_tf32(Xs[(k + 4) * 1032 + px + 8]);
        pb[idx] = v;
    }
}

// persistent: each CTA loops over units u = (b<<5) | co_group
__global__ void __launch_bounds__(512, 1)
fused_kernel(const int* __restrict__ hh, const int* __restrict__ wwp,
             const float* __restrict__ weight, const float* __restrict__ bias,
             float* __restrict__ out)
{
    extern __shared__ char smem[];
    float* Ys = (float*)smem;
    float* red = (float*)(smem + SM_RED);
    const int tid = threadIdx.x, wid = tid >> 5, l = tid & 31;
    const int lq = l & 3, ln = l >> 2;
    const int px0 = wid * 64;
    const int co_l = tid >> 7, lane128 = tid & 127;

    for (int u = blockIdx.x; u < NUNITS; u += gridDim.x) {
        const int co0 = (u & 31) * TC;
        const int b = u >> 5;

        // zero W pad rows 36..39 (first 64 words of each) + fill W rows 0..35
        for (int i = tid; i < 256; i += 512)
            *(uint32_t*)(smem + SM_W + (36 + (i >> 6)) * 272 + (i & 63) * 4) = 0u;
        for (int i = tid; i < TC * CINN * 9; i += 512) {
            int c = i / 576, r = i - c * 576, ci = r / 9, tap = r - ci * 9;
            float w = weight[(co0 + c) * 576 + ci * 9 + tap];
            *(uint32_t*)(smem + SM_W + (tap * 4 + c) * 272 + ci * 4) = to_tf32(w);
        }
        __syncthreads();

        float acc[4][5][4];
#pragma unroll
        for (int mt = 0; mt < 4; mt++)
#pragma unroll
            for (int nt = 0; nt < 5; nt++)
#pragma unroll
                for (int k = 0; k < 4; k++) acc[mt][nt][k] = 0.f;

#pragma unroll 1
        for (int ch = 0; ch < 4; ch++) {
            const uint4* pb = A_g + (size_t)(b * 4 + ch) * 4096;
#pragma unroll
            for (int kk = 0; kk < 2; kk++) {
                uint32_t bf[5][2];
#pragma unroll
                for (int nt = 0; nt < 5; nt++) {
                    int base = SM_W + (nt * 8 + ln) * 272 + (ch * 16 + kk * 8 + lq) * 4;
                    bf[nt][0] = *(uint32_t*)(smem + base);
                    bf[nt][1] = *(uint32_t*)(smem + base + 16);
                }
#pragma unroll
                for (int mt = 0; mt < 4; mt++) {
                    uint4 a = pb[(wid * 4 + mt) * 64 + kk * 32 + l];
#pragma unroll
                    for (int nt = 0; nt < 5; nt++)
                        mma_tf32(acc[mt][nt], (const uint32_t*)&a, bf[nt]);
                }
            }
        }
        __syncthreads();   // W reads done; Ys rows 32..35 (aliasing W) may be written

        // readout: D frag m16n8: d0/d1 row ln cols 2lq,2lq+1; d2/d3 row ln+8
#pragma unroll
        for (int mt = 0; mt < 4; mt++)
#pragma unroll
            for (int nt = 0; nt < 5; nt++) {
                int c0 = nt * 8 + 2 * lq;
                if (nt == 4 && lq >= 2) continue;  // cols 36..39 unused
                int px = px0 + mt * 16 + ln;
                Ys[c0 * NPIX + px]            = acc[mt][nt][0];
                Ys[(c0 + 1) * NPIX + px]      = acc[mt][nt][1];
                Ys[c0 * NPIX + px + 8]        = acc[mt][nt][2];
                Ys[(c0 + 1) * NPIX + px + 8]  = acc[mt][nt][3];
            }
        __syncthreads();

        // ---- combine: center row+column statically specialized, uniform v-guards ----
        int dh = 96 / hh[b];  if (dh < 1) dh = 1;
        int dw = 96 / wwp[b]; if (dw < 1) dw = 1;
        int rv[3][2]; bool rsel[3][3];
        int dcl0, dch0, dcl2, dch2; bool cdup0, cdup2, csel0[3], csel2[3];
#pragma unroll
        for (int k = 0; k < 3; k++) {
            int d0 = fd3((k - 1) * dh), d1 = fd3(1 + (k - 1) * dh), d2 = fd3(2 + (k - 1) * dh);
            rv[k][0] = d0; rv[k][1] = d2;
            rsel[k][0] = false; rsel[k][1] = (d1 != d0); rsel[k][2] = (d2 != d0);
        }
        {
            int c0 = fd3(-dw), c1 = fd3(1 - dw), c2 = fd3(2 - dw);
            dcl0 = c0; dch0 = c2; cdup0 = (c2 != c0);
            csel0[0] = false; csel0[1] = (c1 != c0); csel0[2] = (c2 != c0);
            int e0 = fd3(dw), e1 = fd3(1 + dw), e2 = fd3(2 + dw);
            dcl2 = e0; dch2 = e2; cdup2 = (e2 != e0);
            csel2[0] = false; csel2[1] = (e1 != e0); csel2[2] = (e2 != e0);
        }
        const bool vneed0 = (rv[0][1] != rv[0][0]);
        const bool vneed2 = (rv[2][1] != rv[2][0]);
        const float bias_v = bias[co0 + co_l];
        float lsum = 0.f, lsq = 0.f;

#pragma unroll 2
        for (int j = 0; j < 8; j++) {
            int pix = lane128 + (j << 7), py = pix >> 5, px = pix & 31;

            // center tap-row (ki=1): row offset 0, always valid; bias folded
            float RS1[3];
            {
                const float* P0 = &Ys[(3 * TC + co_l) * NPIX + py * 32];
                const float* P1 = P0 + TC * NPIX;
                const float* P2 = P1 + TC * NPIX;
                int cA0 = px + dcl0, cA2 = px + dcl2;
                float A0 = ((unsigned)cA0 < 32u) ? P0[cA0] : 0.f;
                float B0 = A0;
                if (cdup0) { int cB = px + dch0; B0 = ((unsigned)cB < 32u) ? P0[cB] : 0.f; }
                float Lc = P1[px];
                float A2 = ((unsigned)cA2 < 32u) ? P2[cA2] : 0.f;
                float B2 = A2;
                if (cdup2) { int cB = px + dch2; B2 = ((unsigned)cB < 32u) ? P2[cB] : 0.f; }
#pragma unroll
                for (int s = 0; s < 3; s++)
                    RS1[s] = bias_v + (Lc + (csel0[s] ? B0 : A0) + (csel2[s] ? B2 : A2));
            }
            // side tap-rows (ki=0,2); v=1 only when offsets differ (CTA-uniform)
            float RS0[2][3], RS2[2][3];
#pragma unroll
            for (int ki = 0; ki < 3; ki += 2) {
                float (*RS)[3] = (ki == 0) ? RS0 : RS2;
                const bool vneed = (ki == 0) ? vneed0 : vneed2;
#pragma unroll
                for (int v = 0; v < 2; v++) {
                    if (v == 1 && !vneed) {
#pragma unroll
                        for (int s = 0; s < 3; s++) RS[1][s] = RS[0][s];
                        break;
                    }
                    int row = py + rv[ki][v];
                    bool rok = (unsigned)row < 32u;
                    int rb = row * 32;
                    const float* P0 = &Ys[(ki * 3 * TC + co_l) * NPIX + rb];
                    const float* P1 = P0 + TC * NPIX;
                    const float* P2 = P1 + TC * NPIX;
                    int cA0 = px + dcl0, cA2 = px + dcl2;
                    float A0 = (rok && (unsigned)cA0 < 32u) ? P0[cA0] : 0.f;
                    float B0 = A0;
                    if (cdup0) { int cB = px + dch0; B0 = (rok && (unsigned)cB < 32u) ? P0[cB] : 0.f; }
                    float Lc = rok ? P1[px] : 0.f;
                    float A2 = (rok && (unsigned)cA2 < 32u) ? P2[cA2] : 0.f;
                    float B2 = A2;
                    if (cdup2) { int cB = px + dch2; B2 = (rok && (unsigned)cB < 32u) ? P2[cB] : 0.f; }
#pragma unroll
                    for (int s = 0; s < 3; s++)
                        RS[v][s] = Lc + (csel0[s] ? B0 : A0) + (csel2[s] ? B2 : A2);
                }
            }
            float mx = -INFINITY;
#pragma unroll
            for (int r = 0; r < 3; r++)
#pragma unroll
                for (int s = 0; s < 3; s++) {
                    float v0 = rsel[0][r] ? RS0[1][s] : RS0[0][s];
                    float v2 = rsel[2][r] ? RS2[1][s] : RS2[0][s];
                    mx = fmaxf(mx, v0 + RS1[s] + v2);
                }
            out[((size_t)b * COUTT + co0 + co_l) * NPIX + pix] = mx;
            lsum += mx; lsq += mx * mx;
        }
#pragma unroll
        for (int o = 16; o > 0; o >>= 1) {
            lsum += __shfl_xor_sync(0xFFFFFFFFu, lsum, o);
            lsq  += __shfl_xor_sync(0xFFFFFFFFu, lsq,  o);
        }
        __syncthreads();
        if (l == 0) { red[wid * 2] = lsum; red[wid * 2 + 1] = lsq; }
        __syncthreads();
        if (tid < TC) {
            int c = tid;
            float s = red[8*c] + red[8*c+2] + red[8*c+4] + red[8*c+6];
            float q = red[8*c+1] + red[8*c+3] + red[8*c+5] + red[8*c+7];
            g_psum[(co0 + c) * BB + b] = s;
            g_psumsq[(co0 + c) * BB + b] = q;
        }
        __syncthreads();  // Ys/red reads done before next unit overwrites
    }
}

// warp-per-channel: grid 4 x 1024 threads = 128 warps
__global__ void __launch_bounds__(1024)
stats_kernel(const float* __restrict__ gamma, const float* __restrict__ beta)
{
    int gw = (blockIdx.x * 1024 + threadIdx.x) >> 5;   // channel 0..127
    int l = threadIdx.x & 31;
    float s = g_psum[gw * BB + l] + g_psum[gw * BB + 32 + l];
    float q = g_psumsq[gw * BB + l] + g_psumsq[gw * BB + 32 + l];
#pragma unroll
    for (int o = 16; o > 0; o >>= 1) {
        s += __shfl_xor_sync(0xFFFFFFFFu, s, o);
        q += __shfl_xor_sync(0xFFFFFFFFu, q, o);
    }
    if (l == 0) {
        const float inv = 1.0f / 65536.0f;
        float mean = s * inv, var = q * inv - mean * mean;
        float sc = gamma[gw] * rsqrtf(var + 1e-5f);
        g_scale[gw] = sc;
        g_shift[gw] = beta[gw] - mean * sc;
    }
}

__global__ void __launch_bounds__(1024)
apply_kernel(float* __restrict__ out)
{
    int i0 = blockIdx.x * 4096 + threadIdx.x;
#pragma unroll
    for (int j = 0; j < 4; j++) {
        int i = i0 + j * 1024;
        int c = (i >> 8) & 127;
        float4 v = ((float4*)out)[i];
        float sc = g_scale[c], sh = g_shift[c];
        v.x = fmaxf(fmaf(v.x, sc, sh), 0.f);
        v.y = fmaxf(fmaf(v.y, sc, sh), 0.f);
        v.z = fmaxf(fmaf(v.z, sc, sh), 0.f);
        v.w = fmaxf(fmaf(v.w, sc, sh), 0.f);
        ((float4*)out)[i] = v;
    }
}

extern "C" void kernel_launch(void* const* d_in, const int* in_sizes, int n_in,
                              void* d_out, int out_size)
{
    const float* x      = (const float*)d_in[0];
    const int*   h      = (const int*)  d_in[1];
    const int*   w      = (const int*)  d_in[2];
    const float* weight = (const float*)d_in[3];
    const float* bias   = (const float*)d_in[4];
    const float* gamma  = (const float*)d_in[5];
    const float* beta   = (const float*)d_in[6];
    float* out = (float*)d_out;

    int nsm = 148;
    cudaDeviceGetAttribute(&nsm, cudaDevAttrMultiProcessorCount, 0);

    cudaFuncSetAttribute(build_A, cudaFuncAttributeMaxDynamicSharedMemorySize, 66048);
    cudaFuncSetAttribute(fused_kernel, cudaFuncAttributeMaxDynamicSharedMemorySize, SMEM_TOTAL);

    build_A<<<dim3(4, BB), 512, 66048>>>(x);
    fused_kernel<<<nsm, 512, SMEM_TOTAL>>>(h, w, weight, bias, out);
    stats_kernel<<<4, 1024>>>(gamma, beta);
    apply_kernel<<<512, 1024>>>(out);
}

// round 11
// speedup vs baseline: 1.3126x; 1.3126x over previous
#include <cuda_runtime.h>
#include <cuda_bf16.h>
#include <math.h>
#include <cstdint>

#define BB 64
#define CINN 64
#define COUTT 128
#define NPIX 1024
#define TC 4

// fused SMEM: Ys[36 c][33 rows][40 cols] f32 = 47520 words = 190080 B (rows 0..31 data with
// 4-col zero halos; row 32 all-zero). W (40 rows x 272B) at 190080. red at 200960.
#define YCS 1320            // c-stride in words (33*40)
#define YRS 40              // row-stride in words
#define ZROW 32
#define SM_W   190080
#define SM_RED 200960
#define SMEM_TOTAL 201088

// A_g: per (b,chunk=16cin) plane of 4096 uint4 in m16n8k8-tf32 fragment order:
// idx = mtile*64 + kk*32 + lane; uint4 = {a0,a1,a2,a3} for px rows mtile*16..+15, k=chunk*16+kk*8..+7
__device__ uint4 A_g[BB * 4 * 4096];
__device__ float g_psum[COUTT * BB];
__device__ float g_psumsq[COUTT * BB];
__device__ float g_scale[COUTT];
__device__ float g_shift[COUTT];

__device__ __forceinline__ void mma_tf32(float* d, const uint32_t* a, const uint32_t* b) {
    asm volatile("mma.sync.aligned.m16n8k8.row.col.f32.tf32.tf32.f32 "
        "{%0,%1,%2,%3}, {%4,%5,%6,%7}, {%8,%9}, {%0,%1,%2,%3};"
        : "+f"(d[0]), "+f"(d[1]), "+f"(d[2]), "+f"(d[3])
        : "r"(a[0]), "r"(a[1]), "r"(a[2]), "r"(a[3]), "r"(b[0]), "r"(b[1]));
}
__device__ __forceinline__ uint32_t to_tf32(float f) {
    uint32_t o;
    asm("cvt.rna.tf32.f32 %0, %1;" : "=r"(o) : "f"(f));
    return o;
}
__device__ __forceinline__ int fd3(int a) { return (a + 24) / 3 - 8; }  // floor(a/3), a>=-24

// ---- prologue: per (chunk,b) emit tf32 A plane in fragment order (verified) ----
__global__ void __launch_bounds__(512) build_A(const float* __restrict__ x)
{
    extern __shared__ float Xs[];   // [16][1032]
    const int tid = threadIdx.x, chunk = blockIdx.x, b = blockIdx.y;
    const float4* xg = (const float4*)(x + (size_t)b * CINN * NPIX + chunk * 16 * NPIX);
#pragma unroll
    for (int j = 0; j < 8; j++) {
        int idx = tid + 512 * j;
        int ci = idx >> 8, px4 = idx & 255;
        *(float4*)(Xs + ci * 1032 + px4 * 4) = xg[idx];
    }
    __syncthreads();
    uint4* pb = A_g + (size_t)(b * 4 + chunk) * 4096;
#pragma unroll
    for (int j = 0; j < 8; j++) {
        int idx = tid + 512 * j;
        int l = idx & 31, t = l & 3, g = l >> 2;
        int kk = (idx >> 5) & 1, mtile = idx >> 6;
        int px = mtile * 16 + g, k = kk * 8 + t;
        uint4 v;
        v.x = to_tf32(Xs[k * 1032 + px]);
        v.y = to_tf32(Xs[k * 1032 + px + 8]);
        v.z = to_tf32(Xs[(k + 4) * 1032 + px]);
        v.w = to_tf32(Xs[(k + 4) * 1032 + px + 8]);
        pb[idx] = v;
    }
}

__global__ void __launch_bounds__(512, 1)
fused_kernel(const int* __restrict__ hh, const int* __restrict__ wwp,
             const float* __restrict__ weight, const float* __restrict__ bias,
             float* __restrict__ out)
{
    extern __shared__ char smem[];
    float* Ys = (float*)smem;
    float* red = (float*)(smem + SM_RED);
    const int tid = threadIdx.x, wid = tid >> 5, l = tid & 31;
    const int b = blockIdx.y, co0 = blockIdx.x * TC;

    // zero Ys column halos (36 c x 32 rows x 8 cols = 9216 words)
    for (int i = tid; i < 9216; i += 512) {
        int c = i >> 8, r = (i >> 3) & 31, k = i & 7;
        int col = (k < 4) ? k : (k + 32);   // 0..3 or 36..39
        Ys[c * YCS + r * YRS + col] = 0.f;
    }
    // zero row 32 (36 c x 40 cols = 1440 words)
    for (int i = tid; i < 1440; i += 512) {
        int c = i / 40, col = i - c * 40;
        Ys[c * YCS + ZROW * YRS + col] = 0.f;
    }
    // zero W pad rows 36..39 (first 64 words each; B-frag reads reach word 63+4)
    for (int i = tid; i < 272; i += 512)
        *(uint32_t*)(smem + SM_W + (36 + (i >> 6)) * 272 + (i & 63) * 4) = 0u;
    // weights tf32: row n = tap*4+c, 272B stride (conflict-free B-frag LDS)
    for (int i = tid; i < TC * CINN * 9; i += 512) {
        int c = i / 576, r = i - c * 576, ci = r / 9, tap = r - ci * 9;
        float w = weight[(co0 + c) * 576 + ci * 9 + tap];
        *(uint32_t*)(smem + SM_W + (tap * 4 + c) * 272 + ci * 4) = to_tf32(w);
    }
    __syncthreads();

    float acc[4][5][4];
#pragma unroll
    for (int mt = 0; mt < 4; mt++)
#pragma unroll
        for (int nt = 0; nt < 5; nt++)
#pragma unroll
            for (int k = 0; k < 4; k++) acc[mt][nt][k] = 0.f;

    const int lq = l & 3, ln = l >> 2;
    const int px0 = wid * 64;
    const int co_l = tid >> 7, lane128 = tid & 127;

#pragma unroll 1
    for (int ch = 0; ch < 4; ch++) {
        const uint4* pb = A_g + (size_t)(b * 4 + ch) * 4096;
#pragma unroll
        for (int kk = 0; kk < 2; kk++) {
            uint32_t bf[5][2];
#pragma unroll
            for (int nt = 0; nt < 5; nt++) {
                int base = SM_W + (nt * 8 + ln) * 272 + (ch * 16 + kk * 8 + lq) * 4;
                bf[nt][0] = *(uint32_t*)(smem + base);
                bf[nt][1] = *(uint32_t*)(smem + base + 16);
            }
#pragma unroll
            for (int mt = 0; mt < 4; mt++) {
                uint4 a = pb[(wid * 4 + mt) * 64 + kk * 32 + l];
#pragma unroll
                for (int nt = 0; nt < 5; nt++)
                    mma_tf32(acc[mt][nt], (const uint32_t*)&a, bf[nt]);
            }
        }
    }
    __syncthreads();

    // readout into padded layout: c-row n -> Ys[n][px>>5][4 + (px&31)]
#pragma unroll
    for (int mt = 0; mt < 4; mt++)
#pragma unroll
        for (int nt = 0; nt < 5; nt++) {
            int c0 = nt * 8 + 2 * lq;
            if (nt == 4 && lq >= 2) continue;  // cols 36..39 unused
            int px = px0 + mt * 16 + ln;
            int base = c0 * YCS + (px >> 5) * YRS + (px & 31) + 4;
            Ys[base]           = acc[mt][nt][0];
            Ys[base + YCS]     = acc[mt][nt][1];
            Ys[base + 8]       = acc[mt][nt][2];
            Ys[base + YCS + 8] = acc[mt][nt][3];
        }
    __syncthreads();

    // ---- combine: padded loads (no per-load predication), center specialization ----
    int dh = 96 / hh[b];  if (dh < 1) dh = 1;
    int dw = 96 / wwp[b]; if (dw < 1) dw = 1;
    int rv[3][2]; bool rsel[3][3];
    int dcl0, dch0, dcl2, dch2; bool cdup0, cdup2, csel0[3], csel2[3];
#pragma unroll
    for (int k = 0; k < 3; k++) {
        int d0 = fd3((k - 1) * dh), d1 = fd3(1 + (k - 1) * dh), d2 = fd3(2 + (k - 1) * dh);
        rv[k][0] = d0; rv[k][1] = d2;
        rsel[k][0] = false; rsel[k][1] = (d1 != d0); rsel[k][2] = (d2 != d0);
    }
    {
        int c0 = fd3(-dw), c1 = fd3(1 - dw), c2 = fd3(2 - dw);
        dcl0 = c0; dch0 = c2; cdup0 = (c2 != c0);
        csel0[0] = false; csel0[1] = (c1 != c0); csel0[2] = (c2 != c0);
        int e0 = fd3(dw), e1 = fd3(1 + dw), e2 = fd3(2 + dw);
        dcl2 = e0; dch2 = e2; cdup2 = (e2 != e0);
        csel2[0] = false; csel2[1] = (e1 != e0); csel2[2] = (e2 != e0);
    }
    const bool vneed0 = (rv[0][1] != rv[0][0]);
    const bool vneed2 = (rv[2][1] != rv[2][0]);
    const float bias_v = bias[co0 + co_l];
    float lsum = 0.f, lsq = 0.f;

#pragma unroll 2
    for (int j = 0; j < 8; j++) {
        int pix = lane128 + (j << 7), py = pix >> 5, px = pix & 31;
        const int colA0 = 4 + px + dcl0, colB0 = 4 + px + dch0;
        const int colC  = 4 + px;
        const int colA2 = 4 + px + dcl2, colB2 = 4 + px + dch2;

        // center tap-row (ki=1): row offset 0, always valid; bias folded
        float RS1[3];
        {
            const float* P0 = &Ys[(3 * TC + co_l) * YCS + py * YRS];
            const float* P1 = P0 + TC * YCS;
            const float* P2 = P1 + TC * YCS;
            float A0 = P0[colA0], B0 = cdup0 ? P0[colB0] : A0;
            float Lc = P1[colC];
            float A2 = P2[colA2], B2 = cdup2 ? P2[colB2] : A2;
#pragma unroll
            for (int s = 0; s < 3; s++)
                RS1[s] = bias_v + (Lc + (csel0[s] ? B0 : A0) + (csel2[s] ? B2 : A2));
        }
        // side tap-rows (ki=0,2); v=1 only when offsets differ (CTA-uniform)
        float RS0[2][3], RS2[2][3];
#pragma unroll
        for (int ki = 0; ki < 3; ki += 2) {
            float (*RS)[3] = (ki == 0) ? RS0 : RS2;
            const bool vneed = (ki == 0) ? vneed0 : vneed2;
#pragma unroll
            for (int v = 0; v < 2; v++) {
                if (v == 1 && !vneed) {
#pragma unroll
                    for (int s = 0; s < 3; s++) RS[1][s] = RS[0][s];
                    break;
                }
                int row = py + rv[ki][v];
                int rowsel = ((unsigned)row < 32u) ? row : ZROW;
                const float* P0 = &Ys[(ki * 3 * TC + co_l) * YCS + rowsel * YRS];
                const float* P1 = P0 + TC * YCS;
                const float* P2 = P1 + TC * YCS;
                float A0 = P0[colA0], B0 = cdup0 ? P0[colB0] : A0;
                float Lc = P1[colC];
                float A2 = P2[colA2], B2 = cdup2 ? P2[colB2] : A2;
#pragma unroll
                for (int s = 0; s < 3; s++)
                    RS[v][s] = Lc + (csel0[s] ? B0 : A0) + (csel2[s] ? B2 : A2);
            }
        }
        float mx = -INFINITY;
#pragma unroll
        for (int r = 0; r < 3; r++)
#pragma unroll
            for (int s = 0; s < 3; s++) {
                float v0 = rsel[0][r] ? RS0[1][s] : RS0[0][s];
                float v2 = rsel[2][r] ? RS2[1][s] : RS2[0][s];
                mx = fmaxf(mx, v0 + RS1[s] + v2);
            }
        out[((size_t)b * COUTT + co0 + co_l) * NPIX + pix] = mx;
        lsum += mx; lsq += mx * mx;
    }
#pragma unroll
    for (int o = 16; o > 0; o >>= 1) {
        lsum += __shfl_xor_sync(0xFFFFFFFFu, lsum, o);
        lsq  += __shfl_xor_sync(0xFFFFFFFFu, lsq,  o);
    }
    __syncthreads();
    if (l == 0) { red[wid * 2] = lsum; red[wid * 2 + 1] = lsq; }
    __syncthreads();
    if (tid < TC) {
        int c = tid;
        float s = red[8*c] + red[8*c+2] + red[8*c+4] + red[8*c+6];
        float q = red[8*c+1] + red[8*c+3] + red[8*c+5] + red[8*c+7];
        g_psum[(co0 + c) * BB + b] = s;
        g_psumsq[(co0 + c) * BB + b] = q;
    }
}

// warp-per-channel: grid 4 x 1024 threads = 128 warps
__global__ void __launch_bounds__(1024)
stats_kernel(const float* __restrict__ gamma, const float* __restrict__ beta)
{
    int gw = (blockIdx.x * 1024 + threadIdx.x) >> 5;   // channel 0..127
    int l = threadIdx.x & 31;
    float s = g_psum[gw * BB + l] + g_psum[gw * BB + 32 + l];
    float q = g_psumsq[gw * BB + l] + g_psumsq[gw * BB + 32 + l];
#pragma unroll
    for (int o = 16; o > 0; o >>= 1) {
        s += __shfl_xor_sync(0xFFFFFFFFu, s, o);
        q += __shfl_xor_sync(0xFFFFFFFFu, q, o);
    }
    if (l == 0) {
        const float inv = 1.0f / 65536.0f;
        float mean = s * inv, var = q * inv - mean * mean;
        float sc = gamma[gw] * rsqrtf(var + 1e-5f);
        g_scale[gw] = sc;
        g_shift[gw] = beta[gw] - mean * sc;
    }
}

__global__ void __launch_bounds__(1024)
apply_kernel(float* __restrict__ out)
{
    int i0 = blockIdx.x * 4096 + threadIdx.x;
#pragma unroll
    for (int j = 0; j < 4; j++) {
        int i = i0 + j * 1024;
        int c = (i >> 8) & 127;
        float4 v = ((float4*)out)[i];
        float sc = g_scale[c], sh = g_shift[c];
        v.x = fmaxf(fmaf(v.x, sc, sh), 0.f);
        v.y = fmaxf(fmaf(v.y, sc, sh), 0.f);
        v.z = fmaxf(fmaf(v.z, sc, sh), 0.f);
        v.w = fmaxf(fmaf(v.w, sc, sh), 0.f);
        ((float4*)out)[i] = v;
    }
}

extern "C" void kernel_launch(void* const* d_in, const int* in_sizes, int n_in,
                              void* d_out, int out_size)
{
    const float* x      = (const float*)d_in[0];
    const int*   h      = (const int*)  d_in[1];
    const int*   w      = (const int*)  d_in[2];
    const float* weight = (const float*)d_in[3];
    const float* bias   = (const float*)d_in[4];
    const float* gamma  = (const float*)d_in[5];
    const float* beta   = (const float*)d_in[6];
    float* out = (float*)d_out;

    cudaFuncSetAttribute(build_A, cudaFuncAttributeMaxDynamicSharedMemorySize, 66048);
    cudaFuncSetAttribute(fused_kernel, cudaFuncAttributeMaxDynamicSharedMemorySize, SMEM_TOTAL);

    build_A<<<dim3(4, BB), 512, 66048>>>(x);
    fused_kernel<<<dim3(COUTT / TC, BB), 512, SMEM_TOTAL>>>(h, w, weight, bias, out);
    stats_kernel<<<4, 1024>>>(gamma, beta);
    apply_kernel<<<512, 1024>>>(out);
}

// round 12
// speedup vs baseline: 1.3777x; 1.0496x over previous
#include <cuda_runtime.h>
#include <cuda_bf16.h>
#include <math.h>
#include <cstdint>

#define BB 64
#define CINN 64
#define COUTT 128
#define NPIX 1024
#define TC 4

// fused SMEM: Ys[9 taps][33 rows][40 cols][4 co] f32 = 190080 B (rows 0..31 data with 4-col
// zero halos each side; row 32 all-zero). W (40 x 272B) at 190080. red (128 f32) at 200960.
#define ZROW 32
#define SM_W   190080
#define SM_RED 200960
#define SMEM_TOTAL 201472

// A_g: per (b,chunk=16cin) plane of 4096 uint4 in m16n8k8-tf32 fragment order:
// idx = mtile*64 + kk*32 + lane; uint4 = {a0,a1,a2,a3} for px rows mtile*16..+15, k=chunk*16+kk*8..+7
__device__ uint4 A_g[BB * 4 * 4096];
__device__ float g_psum[COUTT * BB];
__device__ float g_psumsq[COUTT * BB];
__device__ float g_scale[COUTT];
__device__ float g_shift[COUTT];

__device__ __forceinline__ void mma_tf32(float* d, const uint32_t* a, const uint32_t* b) {
    asm volatile("mma.sync.aligned.m16n8k8.row.col.f32.tf32.tf32.f32 "
        "{%0,%1,%2,%3}, {%4,%5,%6,%7}, {%8,%9}, {%0,%1,%2,%3};"
        : "+f"(d[0]), "+f"(d[1]), "+f"(d[2]), "+f"(d[3])
        : "r"(a[0]), "r"(a[1]), "r"(a[2]), "r"(a[3]), "r"(b[0]), "r"(b[1]));
}
__device__ __forceinline__ uint32_t to_tf32(float f) {
    uint32_t o;
    asm("cvt.rna.tf32.f32 %0, %1;" : "=r"(o) : "f"(f));
    return o;
}
__device__ __forceinline__ int fd3(int a) { return (a + 24) / 3 - 8; }  // floor(a/3), a>=-24

__device__ __forceinline__ float4 f4sel(bool c, float4 b, float4 a) {
    float4 r;
    r.x = c ? b.x : a.x; r.y = c ? b.y : a.y; r.z = c ? b.z : a.z; r.w = c ? b.w : a.w;
    return r;
}
__device__ __forceinline__ float4 f4add(float4 a, float4 b) {
    float4 r;
    r.x = a.x + b.x; r.y = a.y + b.y; r.z = a.z + b.z; r.w = a.w + b.w;
    return r;
}
__device__ __forceinline__ float4 f4max(float4 a, float4 b) {
    float4 r;
    r.x = fmaxf(a.x, b.x); r.y = fmaxf(a.y, b.y); r.z = fmaxf(a.z, b.z); r.w = fmaxf(a.w, b.w);
    return r;
}

// ---- prologue: per (chunk,b) emit tf32 A plane in fragment order (verified) ----
__global__ void __launch_bounds__(512) build_A(const float* __restrict__ x)
{
    extern __shared__ float Xs[];   // [16][1032]
    const int tid = threadIdx.x, chunk = blockIdx.x, b = blockIdx.y;
    const float4* xg = (const float4*)(x + (size_t)b * CINN * NPIX + chunk * 16 * NPIX);
#pragma unroll
    for (int j = 0; j < 8; j++) {
        int idx = tid + 512 * j;
        int ci = idx >> 8, px4 = idx & 255;
        *(float4*)(Xs + ci * 1032 + px4 * 4) = xg[idx];
    }
    __syncthreads();
    uint4* pb = A_g + (size_t)(b * 4 + chunk) * 4096;
#pragma unroll
    for (int j = 0; j < 8; j++) {
        int idx = tid + 512 * j;
        int l = idx & 31, t = l & 3, g = l >> 2;
        int kk = (idx >> 5) & 1, mtile = idx >> 6;
        int px = mtile * 16 + g, k = kk * 8 + t;
        uint4 v;
        v.x = to_tf32(Xs[k * 1032 + px]);
        v.y = to_tf32(Xs[k * 1032 + px + 8]);
        v.z = to_tf32(Xs[(k + 4) * 1032 + px]);
        v.w = to_tf32(Xs[(k + 4) * 1032 + px + 8]);
        pb[idx] = v;
    }
}

__global__ void __launch_bounds__(512, 1)
fused_kernel(const int* __restrict__ hh, const int* __restrict__ wwp,
             const float* __restrict__ weight, const float* __restrict__ bias,
             float* __restrict__ out)
{
    extern __shared__ char smem[];
    float* Y = (float*)smem;
    float4* Y4 = (float4*)smem;
    float* red = (float*)(smem + SM_RED);
    const int tid = threadIdx.x, wid = tid >> 5, l = tid & 31;
    const int b = blockIdx.y, co0 = blockIdx.x * TC;

    // zero column halos: 9 taps x 32 rows x 8 halo-cols x 4 co = 9216 words
    for (int i = tid; i < 9216; i += 512) {
        int tap = i >> 10, rem = i & 1023, r = rem >> 5, k = (rem >> 2) & 7, co = i & 3;
        int col = (k < 4) ? k : (k + 32);
        Y[((tap * 33 + r) * 40 + col) * 4 + co] = 0.f;
    }
    // zero row 32: 9 taps x 160 words
    for (int i = tid; i < 1440; i += 512) {
        int tap = i / 160, rem = i - tap * 160;
        Y[(tap * 33 + ZROW) * 160 + rem] = 0.f;
    }
    // zero W pad rows 36..39 (first 68 words each)
    for (int i = tid; i < 272; i += 512)
        *(uint32_t*)(smem + SM_W + (36 + (i >> 6)) * 272 + (i & 63) * 4) = 0u;
    // weights tf32: row n = tap*4+c, 272B stride (conflict-free B-frag LDS)
    for (int i = tid; i < TC * CINN * 9; i += 512) {
        int c = i / 576, r = i - c * 576, ci = r / 9, tap = r - ci * 9;
        float w = weight[(co0 + c) * 576 + ci * 9 + tap];
        *(uint32_t*)(smem + SM_W + (tap * 4 + c) * 272 + ci * 4) = to_tf32(w);
    }
    __syncthreads();

    float acc[4][5][4];
#pragma unroll
    for (int mt = 0; mt < 4; mt++)
#pragma unroll
        for (int nt = 0; nt < 5; nt++)
#pragma unroll
            for (int k = 0; k < 4; k++) acc[mt][nt][k] = 0.f;

    const int lq = l & 3, ln = l >> 2;
    const int px0 = wid * 64;

#pragma unroll 1
    for (int ch = 0; ch < 4; ch++) {
        const uint4* pb = A_g + (size_t)(b * 4 + ch) * 4096;
#pragma unroll
        for (int kk = 0; kk < 2; kk++) {
            uint32_t bf[5][2];
#pragma unroll
            for (int nt = 0; nt < 5; nt++) {
                int base = SM_W + (nt * 8 + ln) * 272 + (ch * 16 + kk * 8 + lq) * 4;
                bf[nt][0] = *(uint32_t*)(smem + base);
                bf[nt][1] = *(uint32_t*)(smem + base + 16);
            }
#pragma unroll
            for (int mt = 0; mt < 4; mt++) {
                uint4 a = pb[(wid * 4 + mt) * 64 + kk * 32 + l];
#pragma unroll
                for (int nt = 0; nt < 5; nt++)
                    mma_tf32(acc[mt][nt], (const uint32_t*)&a, bf[nt]);
            }
        }
    }
    __syncthreads();

    // readout into [tap][row][col][co]: c-row n = tap*4+co
#pragma unroll
    for (int mt = 0; mt < 4; mt++)
#pragma unroll
        for (int nt = 0; nt < 5; nt++) {
            int c0 = nt * 8 + 2 * lq;
            if (nt == 4 && lq >= 2) continue;  // c 36..39 unused
            int tap = c0 >> 2, co = c0 & 3;
            int px = px0 + mt * 16 + ln;
            int base = ((tap * 33 + (px >> 5)) * 40 + (px & 31) + 4) * 4 + co;
            Y[base]          = acc[mt][nt][0];
            Y[base + 1]      = acc[mt][nt][1];
            Y[base + 32]     = acc[mt][nt][2];  // col +8
            Y[base + 33]     = acc[mt][nt][3];
        }
    __syncthreads();

    // ---- combine: float4 over 4 co, padded loads, center specialization ----
    int dh = 96 / hh[b];  if (dh < 1) dh = 1;
    int dw = 96 / wwp[b]; if (dw < 1) dw = 1;
    int rv[3][2]; bool rsel[3][3];
    int dcl0, dch0, dcl2, dch2; bool cdup0, cdup2, csel0[3], csel2[3];
#pragma unroll
    for (int k = 0; k < 3; k++) {
        int d0 = fd3((k - 1) * dh), d1 = fd3(1 + (k - 1) * dh), d2 = fd3(2 + (k - 1) * dh);
        rv[k][0] = d0; rv[k][1] = d2;
        rsel[k][0] = false; rsel[k][1] = (d1 != d0); rsel[k][2] = (d2 != d0);
    }
    {
        int c0 = fd3(-dw), c1 = fd3(1 - dw), c2 = fd3(2 - dw);
        dcl0 = c0; dch0 = c2; cdup0 = (c2 != c0);
        csel0[0] = false; csel0[1] = (c1 != c0); csel0[2] = (c2 != c0);
        int e0 = fd3(dw), e1 = fd3(1 + dw), e2 = fd3(2 + dw);
        dcl2 = e0; dch2 = e2; cdup2 = (e2 != e0);
        csel2[0] = false; csel2[1] = (e1 != e0); csel2[2] = (e2 != e0);
    }
    const bool vneed0 = (rv[0][1] != rv[0][0]);
    const bool vneed2 = (rv[2][1] != rv[2][0]);
    const float4 bias4 = *(const float4*)&bias[co0];
    float4 lsum4 = make_float4(0.f, 0.f, 0.f, 0.f);
    float4 lsq4  = make_float4(0.f, 0.f, 0.f, 0.f);

#pragma unroll 1
    for (int j = 0; j < 2; j++) {
        int pix = tid + (j << 9), py = pix >> 5, px = pix & 31;
        const int colA0 = 4 + px + dcl0, colB0 = 4 + px + dch0;
        const int colC  = 4 + px;
        const int colA2 = 4 + px + dcl2, colB2 = 4 + px + dch2;

        // center tap-row (ki=1, taps 3/4/5): row offset 0; bias folded
        float4 RS1[3];
        {
            int r3 = (3 * 33 + py) * 40, r4 = r3 + 1320, r5 = r4 + 1320;
            float4 A0 = Y4[r3 + colA0];
            float4 B0 = cdup0 ? Y4[r3 + colB0] : A0;
            float4 Lc = Y4[r4 + colC];
            float4 A2 = Y4[r5 + colA2];
            float4 B2 = cdup2 ? Y4[r5 + colB2] : A2;
#pragma unroll
            for (int s = 0; s < 3; s++)
                RS1[s] = f4add(bias4, f4add(Lc,
                          f4add(f4sel(csel0[s], B0, A0), f4sel(csel2[s], B2, A2))));
        }
        // side tap-rows (ki=0: taps 0/1/2; ki=2: taps 6/7/8)
        float4 RS0[2][3], RS2[2][3];
#pragma unroll
        for (int ki = 0; ki < 3; ki += 2) {
            float4 (*RS)[3] = (ki == 0) ? RS0 : RS2;
            const bool vneed = (ki == 0) ? vneed0 : vneed2;
#pragma unroll
            for (int v = 0; v < 2; v++) {
                if (v == 1 && !vneed) {
#pragma unroll
                    for (int s = 0; s < 3; s++) RS[1][s] = RS[0][s];
                    break;
                }
                int row = py + rv[ki][v];
                int rowsel = ((unsigned)row < 32u) ? row : ZROW;
                int t0 = ((ki * 3) * 33 + rowsel) * 40, t1 = t0 + 1320, t2 = t1 + 1320;
                float4 A0 = Y4[t0 + colA0];
                float4 B0 = cdup0 ? Y4[t0 + colB0] : A0;
                float4 Lc = Y4[t1 + colC];
                float4 A2 = Y4[t2 + colA2];
                float4 B2 = cdup2 ? Y4[t2 + colB2] : A2;
#pragma unroll
                for (int s = 0; s < 3; s++)
                    RS[v][s] = f4add(Lc,
                        f4add(f4sel(csel0[s], B0, A0), f4sel(csel2[s], B2, A2)));
            }
        }
        float4 mx = make_float4(-INFINITY, -INFINITY, -INFINITY, -INFINITY);
#pragma unroll
        for (int r = 0; r < 3; r++)
#pragma unroll
            for (int s = 0; s < 3; s++) {
                float4 v0 = rsel[0][r] ? RS0[1][s] : RS0[0][s];
                float4 v2 = rsel[2][r] ? RS2[1][s] : RS2[0][s];
                mx = f4max(mx, f4add(v0, f4add(RS1[s], v2)));
            }
        float* ob = out + ((size_t)b * COUTT + co0) * NPIX + pix;
        ob[0]            = mx.x;
        ob[NPIX]         = mx.y;
        ob[2 * NPIX]     = mx.z;
        ob[3 * NPIX]     = mx.w;
        lsum4 = f4add(lsum4, mx);
        lsq4.x += mx.x * mx.x; lsq4.y += mx.y * mx.y;
        lsq4.z += mx.z * mx.z; lsq4.w += mx.w * mx.w;
    }
#pragma unroll
    for (int o = 16; o > 0; o >>= 1) {
        lsum4.x += __shfl_xor_sync(0xFFFFFFFFu, lsum4.x, o);
        lsum4.y += __shfl_xor_sync(0xFFFFFFFFu, lsum4.y, o);
        lsum4.z += __shfl_xor_sync(0xFFFFFFFFu, lsum4.z, o);
        lsum4.w += __shfl_xor_sync(0xFFFFFFFFu, lsum4.w, o);
        lsq4.x  += __shfl_xor_sync(0xFFFFFFFFu, lsq4.x, o);
        lsq4.y  += __shfl_xor_sync(0xFFFFFFFFu, lsq4.y, o);
        lsq4.z  += __shfl_xor_sync(0xFFFFFFFFu, lsq4.z, o);
        lsq4.w  += __shfl_xor_sync(0xFFFFFFFFu, lsq4.w, o);
    }
    __syncthreads();
    if (l == 0) {
        float* rw = red + wid * 8;
        rw[0] = lsum4.x; rw[1] = lsq4.x;
        rw[2] = lsum4.y; rw[3] = lsq4.y;
        rw[4] = lsum4.z; rw[5] = lsq4.z;
        rw[6] = lsum4.w; rw[7] = lsq4.w;
    }
    __syncthreads();
    if (tid < TC) {
        float s = 0.f, q = 0.f;
#pragma unroll
        for (int wdx = 0; wdx < 16; wdx++) {
            s += red[wdx * 8 + tid * 2];
            q += red[wdx * 8 + tid * 2 + 1];
        }
        g_psum[(co0 + tid) * BB + b] = s;
        g_psumsq[(co0 + tid) * BB + b] = q;
    }
}

// warp-per-channel: grid 4 x 1024 threads = 128 warps
__global__ void __launch_bounds__(1024)
stats_kernel(const float* __restrict__ gamma, const float* __restrict__ beta)
{
    int gw = (blockIdx.x * 1024 + threadIdx.x) >> 5;   // channel 0..127
    int l = threadIdx.x & 31;
    float s = g_psum[gw * BB + l] + g_psum[gw * BB + 32 + l];
    float q = g_psumsq[gw * BB + l] + g_psumsq[gw * BB + 32 + l];
#pragma unroll
    for (int o = 16; o > 0; o >>= 1) {
        s += __shfl_xor_sync(0xFFFFFFFFu, s, o);
        q += __shfl_xor_sync(0xFFFFFFFFu, q, o);
    }
    if (l == 0) {
        const float inv = 1.0f / 65536.0f;
        float mean = s * inv, var = q * inv - mean * mean;
        float sc = gamma[gw] * rsqrtf(var + 1e-5f);
        g_scale[gw] = sc;
        g_shift[gw] = beta[gw] - mean * sc;
    }
}

__global__ void __launch_bounds__(1024)
apply_kernel(float* __restrict__ out)
{
    int i = blockIdx.x * 1024 + threadIdx.x;   // grid 2048 -> one float4 per thread
    int c = (i >> 8) & 127;
    float4 v = ((float4*)out)[i];
    float sc = g_scale[c], sh = g_shift[c];
    v.x = fmaxf(fmaf(v.x, sc, sh), 0.f);
    v.y = fmaxf(fmaf(v.y, sc, sh), 0.f);
    v.z = fmaxf(fmaf(v.z, sc, sh), 0.f);
    v.w = fmaxf(fmaf(v.w, sc, sh), 0.f);
    ((float4*)out)[i] = v;
}

extern "C" void kernel_launch(void* const* d_in, const int* in_sizes, int n_in,
                              void* d_out, int out_size)
{
    const float* x      = (const float*)d_in[0];
    const int*   h      = (const int*)  d_in[1];
    const int*   w      = (const int*)  d_in[2];
    const float* weight = (const float*)d_in[3];
    const float* bias   = (const float*)d_in[4];
    const float* gamma  = (const float*)d_in[5];
    const float* beta   = (const float*)d_in[6];
    float* out = (float*)d_out;

    cudaFuncSetAttribute(build_A, cudaFuncAttributeMaxDynamicSharedMemorySize, 66048);
    cudaFuncSetAttribute(fused_kernel, cudaFuncAttributeMaxDynamicSharedMemorySize, SMEM_TOTAL);

    build_A<<<dim3(4, BB), 512, 66048>>>(x);
    fused_kernel<<<dim3(COUTT / TC, BB), 512, SMEM_TOTAL>>>(h, w, weight, bias, out);
    stats_kernel<<<4, 1024>>>(gamma, beta);
    apply_kernel<<<2048, 1024>>>(out);
}

// round 13
// speedup vs baseline: 1.5899x; 1.1541x over previous
#include <cuda_runtime.h>
#include <cuda_fp16.h>
#include <math.h>
#include <cstdint>

#define BB 64
#define CINN 64
#define COUTT 128
#define NPIX 1024
#define TC 4

// fused SMEM: Ys[9 taps][33 rows][40 cols][4 co] f32 = 190080 B (rows 0..31 data, 4-col zero
// halos; row 32 all-zero). W fp16 (40 rows x 144B) at 190080. red (128 f32) at 195968.
#define ZROW 32
#define SM_W   190080
#define SM_RED 195968
#define SMEM_TOTAL 196480

// A_g: per (b,kstep=16cin) plane of 2048 uint4 in m16n8k16-fp16 A-fragment order:
// idx = mtile*32 + lane; uint4 = {a0,a1,a2,a3}, lane(t=l&3,g=l>>2):
// a0={x[g][2t],x[g][2t+1]} a1={x[g+8][2t],..} a2={x[g][2t+8],..} a3={x[g+8][2t+8],..}
__device__ uint4 A_g[BB * 4 * 2048];
__device__ float g_psum[COUTT * BB];
__device__ float g_psumsq[COUTT * BB];
__device__ float g_scale[COUTT];
__device__ float g_shift[COUTT];

__device__ __forceinline__ void mma_f16(float* d, const uint32_t* a, const uint32_t* b) {
    asm volatile("mma.sync.aligned.m16n8k16.row.col.f32.f16.f16.f32 "
        "{%0,%1,%2,%3}, {%4,%5,%6,%7}, {%8,%9}, {%0,%1,%2,%3};"
        : "+f"(d[0]), "+f"(d[1]), "+f"(d[2]), "+f"(d[3])
        : "r"(a[0]), "r"(a[1]), "r"(a[2]), "r"(a[3]), "r"(b[0]), "r"(b[1]));
}
__device__ __forceinline__ uint32_t pkh(float a, float b) {
    __half2 h = __floats2half2_rn(a, b);
    return *(uint32_t*)&h;
}
__device__ __forceinline__ int fd3(int a) { return (a + 24) / 3 - 8; }  // floor(a/3), a>=-24

__device__ __forceinline__ float4 f4sel(bool c, float4 b, float4 a) {
    float4 r;
    r.x = c ? b.x : a.x; r.y = c ? b.y : a.y; r.z = c ? b.z : a.z; r.w = c ? b.w : a.w;
    return r;
}
__device__ __forceinline__ float4 f4add(float4 a, float4 b) {
    float4 r;
    r.x = a.x + b.x; r.y = a.y + b.y; r.z = a.z + b.z; r.w = a.w + b.w;
    return r;
}
__device__ __forceinline__ float4 f4max(float4 a, float4 b) {
    float4 r;
    r.x = fmaxf(a.x, b.x); r.y = fmaxf(a.y, b.y); r.z = fmaxf(a.z, b.z); r.w = fmaxf(a.w, b.w);
    return r;
}

// ---- prologue: per (kstep=16cin, b) emit fp16 A plane in m16n8k16 fragment order ----
__global__ void __launch_bounds__(512) build_A(const float* __restrict__ x)
{
    extern __shared__ float Xs[];   // [16][1032]
    const int tid = threadIdx.x, ks = blockIdx.x, b = blockIdx.y;
    const float4* xg = (const float4*)(x + (size_t)b * CINN * NPIX + ks * 16 * NPIX);
#pragma unroll
    for (int j = 0; j < 8; j++) {
        int idx = tid + 512 * j;
        int ci = idx >> 8, px4 = idx & 255;
        *(float4*)(Xs + ci * 1032 + px4 * 4) = xg[idx];
    }
    __syncthreads();
    uint4* pb = A_g + (size_t)(b * 4 + ks) * 2048;
#pragma unroll
    for (int j = 0; j < 4; j++) {
        int idx = tid + 512 * j;
        int l = idx & 31, t = l & 3, g = l >> 2;
        int mtile = idx >> 5;
        int px = mtile * 16 + g;
        uint4 v;
        v.x = pkh(Xs[(2 * t) * 1032 + px],     Xs[(2 * t + 1) * 1032 + px]);
        v.y = pkh(Xs[(2 * t) * 1032 + px + 8], Xs[(2 * t + 1) * 1032 + px + 8]);
        v.z = pkh(Xs[(2 * t + 8) * 1032 + px],     Xs[(2 * t + 9) * 1032 + px]);
        v.w = pkh(Xs[(2 * t + 8) * 1032 + px + 8], Xs[(2 * t + 9) * 1032 + px + 8]);
        pb[idx] = v;
    }
}

__global__ void __launch_bounds__(512, 1)
fused_kernel(const int* __restrict__ hh, const int* __restrict__ wwp,
             const float* __restrict__ weight, const float* __restrict__ bias,
             float* __restrict__ out)
{
    extern __shared__ char smem[];
    float* Y = (float*)smem;
    float4* Y4 = (float4*)smem;
    float* red = (float*)(smem + SM_RED);
    const int tid = threadIdx.x, wid = tid >> 5, l = tid & 31;
    const int b = blockIdx.y, co0 = blockIdx.x * TC;

    // zero column halos: 9 taps x 32 rows x 8 halo-cols x 4 co = 9216 words
    for (int i = tid; i < 9216; i += 512) {
        int tap = i >> 10, rem = i & 1023, r = rem >> 5, k = (rem >> 2) & 7, co = i & 3;
        int col = (k < 4) ? k : (k + 32);
        Y[((tap * 33 + r) * 40 + col) * 4 + co] = 0.f;
    }
    // zero row 32: 9 taps x 160 words
    for (int i = tid; i < 1440; i += 512) {
        int tap = i / 160, rem = i - tap * 160;
        Y[(tap * 33 + ZROW) * 160 + rem] = 0.f;
    }
    // zero W pad rows 36..39 (36 words each)
    for (int i = tid; i < 144; i += 512)
        *(uint32_t*)(smem + SM_W + (36 + i / 36) * 144 + (i % 36) * 4) = 0u;
    // weights fp16: row n = tap*4+c, 144B stride (4*ln+lq bank pattern, conflict-free)
    for (int i = tid; i < TC * CINN * 9; i += 512) {
        int c = i / 576, r = i - c * 576, ci = r / 9, tap = r - ci * 9;
        float w = weight[(co0 + c) * 576 + ci * 9 + tap];
        *(__half*)(smem + SM_W + (tap * 4 + c) * 144 + ci * 2) = __float2half_rn(w);
    }
    __syncthreads();

    float acc[4][5][4];
#pragma unroll
    for (int mt = 0; mt < 4; mt++)
#pragma unroll
        for (int nt = 0; nt < 5; nt++)
#pragma unroll
            for (int k = 0; k < 4; k++) acc[mt][nt][k] = 0.f;

    const int lq = l & 3, ln = l >> 2;
    const int px0 = wid * 64;

#pragma unroll 1
    for (int ks = 0; ks < 4; ks++) {
        const uint4* pb = A_g + (size_t)(b * 4 + ks) * 2048;
        uint32_t bf[5][2];
#pragma unroll
        for (int nt = 0; nt < 5; nt++) {
            int base = SM_W + (nt * 8 + ln) * 144 + (ks * 16 + 2 * lq) * 2;
            bf[nt][0] = *(uint32_t*)(smem + base);
            bf[nt][1] = *(uint32_t*)(smem + base + 16);
        }
#pragma unroll
        for (int mt = 0; mt < 4; mt++) {
            uint4 a = pb[(wid * 4 + mt) * 32 + l];
#pragma unroll
            for (int nt = 0; nt < 5; nt++)
                mma_f16(acc[mt][nt], (const uint32_t*)&a, bf[nt]);
        }
    }
    __syncthreads();

    // readout into [tap][row][col][co]: c-row n = tap*4+co
#pragma unroll
    for (int mt = 0; mt < 4; mt++)
#pragma unroll
        for (int nt = 0; nt < 5; nt++) {
            int c0 = nt * 8 + 2 * lq;
            if (nt == 4 && lq >= 2) continue;  // c 36..39 unused
            int tap = c0 >> 2, co = c0 & 3;
            int px = px0 + mt * 16 + ln;
            int base = ((tap * 33 + (px >> 5)) * 40 + (px & 31) + 4) * 4 + co;
            Y[base]      = acc[mt][nt][0];
            Y[base + 1]  = acc[mt][nt][1];
            Y[base + 32] = acc[mt][nt][2];  // col +8
            Y[base + 33] = acc[mt][nt][3];
        }
    __syncthreads();

    // ---- combine: float4 over 4 co, padded loads, center specialization (verified) ----
    int dh = 96 / hh[b];  if (dh < 1) dh = 1;
    int dw = 96 / wwp[b]; if (dw < 1) dw = 1;
    int rv[3][2]; bool rsel[3][3];
    int dcl0, dch0, dcl2, dch2; bool cdup0, cdup2, csel0[3], csel2[3];
#pragma unroll
    for (int k = 0; k < 3; k++) {
        int d0 = fd3((k - 1) * dh), d1 = fd3(1 + (k - 1) * dh), d2 = fd3(2 + (k - 1) * dh);
        rv[k][0] = d0; rv[k][1] = d2;
        rsel[k][0] = false; rsel[k][1] = (d1 != d0); rsel[k][2] = (d2 != d0);
    }
    {
        int c0 = fd3(-dw), c1 = fd3(1 - dw), c2 = fd3(2 - dw);
        dcl0 = c0; dch0 = c2; cdup0 = (c2 != c0);
        csel0[0] = false; csel0[1] = (c1 != c0); csel0[2] = (c2 != c0);
        int e0 = fd3(dw), e1 = fd3(1 + dw), e2 = fd3(2 + dw);
        dcl2 = e0; dch2 = e2; cdup2 = (e2 != e0);
        csel2[0] = false; csel2[1] = (e1 != e0); csel2[2] = (e2 != e0);
    }
    const bool vneed0 = (rv[0][1] != rv[0][0]);
    const bool vneed2 = (rv[2][1] != rv[2][0]);
    const float4 bias4 = *(const float4*)&bias[co0];
    float4 lsum4 = make_float4(0.f, 0.f, 0.f, 0.f);
    float4 lsq4  = make_float4(0.f, 0.f, 0.f, 0.f);

#pragma unroll 1
    for (int j = 0; j < 2; j++) {
        int pix = tid + (j << 9), py = pix >> 5, px = pix & 31;
        const int colA0 = 4 + px + dcl0, colB0 = 4 + px + dch0;
        const int colC  = 4 + px;
        const int colA2 = 4 + px + dcl2, colB2 = 4 + px + dch2;

        float4 RS1[3];
        {
            int r3 = (3 * 33 + py) * 40, r4 = r3 + 1320, r5 = r4 + 1320;
            float4 A0 = Y4[r3 + colA0];
            float4 B0 = cdup0 ? Y4[r3 + colB0] : A0;
            float4 Lc = Y4[r4 + colC];
            float4 A2 = Y4[r5 + colA2];
            float4 B2 = cdup2 ? Y4[r5 + colB2] : A2;
#pragma unroll
            for (int s = 0; s < 3; s++)
                RS1[s] = f4add(bias4, f4add(Lc,
                          f4add(f4sel(csel0[s], B0, A0), f4sel(csel2[s], B2, A2))));
        }
        float4 RS0[2][3], RS2[2][3];
#pragma unroll
        for (int ki = 0; ki < 3; ki += 2) {
            float4 (*RS)[3] = (ki == 0) ? RS0 : RS2;
            const bool vneed = (ki == 0) ? vneed0 : vneed2;
#pragma unroll
            for (int v = 0; v < 2; v++) {
                if (v == 1 && !vneed) {
#pragma unroll
                    for (int s = 0; s < 3; s++) RS[1][s] = RS[0][s];
                    break;
                }
                int row = py + rv[ki][v];
                int rowsel = ((unsigned)row < 32u) ? row : ZROW;
                int t0 = ((ki * 3) * 33 + rowsel) * 40, t1 = t0 + 1320, t2 = t1 + 1320;
                float4 A0 = Y4[t0 + colA0];
                float4 B0 = cdup0 ? Y4[t0 + colB0] : A0;
                float4 Lc = Y4[t1 + colC];
                float4 A2 = Y4[t2 + colA2];
                float4 B2 = cdup2 ? Y4[t2 + colB2] : A2;
#pragma unroll
                for (int s = 0; s < 3; s++)
                    RS[v][s] = f4add(Lc,
                        f4add(f4sel(csel0[s], B0, A0), f4sel(csel2[s], B2, A2)));
            }
        }
        float4 mx = make_float4(-INFINITY, -INFINITY, -INFINITY, -INFINITY);
#pragma unroll
        for (int r = 0; r < 3; r++)
#pragma unroll
            for (int s = 0; s < 3; s++) {
                float4 v0 = rsel[0][r] ? RS0[1][s] : RS0[0][s];
                float4 v2 = rsel[2][r] ? RS2[1][s] : RS2[0][s];
                mx = f4max(mx, f4add(v0, f4add(RS1[s], v2)));
            }
        float* ob = out + ((size_t)b * COUTT + co0) * NPIX + pix;
        ob[0]        = mx.x;
        ob[NPIX]     = mx.y;
        ob[2 * NPIX] = mx.z;
        ob[3 * NPIX] = mx.w;
        lsum4 = f4add(lsum4, mx);
        lsq4.x += mx.x * mx.x; lsq4.y += mx.y * mx.y;
        lsq4.z += mx.z * mx.z; lsq4.w += mx.w * mx.w;
    }
#pragma unroll
    for (int o = 16; o > 0; o >>= 1) {
        lsum4.x += __shfl_xor_sync(0xFFFFFFFFu, lsum4.x, o);
        lsum4.y += __shfl_xor_sync(0xFFFFFFFFu, lsum4.y, o);
        lsum4.z += __shfl_xor_sync(0xFFFFFFFFu, lsum4.z, o);
        lsum4.w += __shfl_xor_sync(0xFFFFFFFFu, lsum4.w, o);
        lsq4.x  += __shfl_xor_sync(0xFFFFFFFFu, lsq4.x, o);
        lsq4.y  += __shfl_xor_sync(0xFFFFFFFFu, lsq4.y, o);
        lsq4.z  += __shfl_xor_sync(0xFFFFFFFFu, lsq4.z, o);
        lsq4.w  += __shfl_xor_sync(0xFFFFFFFFu, lsq4.w, o);
    }
    __syncthreads();
    if (l == 0) {
        float* rw = red + wid * 8;
        rw[0] = lsum4.x; rw[1] = lsq4.x;
        rw[2] = lsum4.y; rw[3] = lsq4.y;
        rw[4] = lsum4.z; rw[5] = lsq4.z;
        rw[6] = lsum4.w; rw[7] = lsq4.w;
    }
    __syncthreads();
    if (tid < TC) {
        float s = 0.f, q = 0.f;
#pragma unroll
        for (int wdx = 0; wdx < 16; wdx++) {
            s += red[wdx * 8 + tid * 2];
            q += red[wdx * 8 + tid * 2 + 1];
        }
        g_psum[(co0 + tid) * BB + b] = s;
        g_psumsq[(co0 + tid) * BB + b] = q;
    }
}

// warp-per-channel: grid 4 x 1024 threads = 128 warps
__global__ void __launch_bounds__(1024)
stats_kernel(const float* __restrict__ gamma, const float* __restrict__ beta)
{
    int gw = (blockIdx.x * 1024 + threadIdx.x) >> 5;   // channel 0..127
    int l = threadIdx.x & 31;
    float s = g_psum[gw * BB + l] + g_psum[gw * BB + 32 + l];
    float q = g_psumsq[gw * BB + l] + g_psumsq[gw * BB + 32 + l];
#pragma unroll
    for (int o = 16; o > 0; o >>= 1) {
        s += __shfl_xor_sync(0xFFFFFFFFu, s, o);
        q += __shfl_xor_sync(0xFFFFFFFFu, q, o);
    }
    if (l == 0) {
        const float inv = 1.0f / 65536.0f;
        float mean = s * inv, var = q * inv - mean * mean;
        float sc = gamma[gw] * rsqrtf(var + 1e-5f);
        g_scale[gw] = sc;
        g_shift[gw] = beta[gw] - mean * sc;
    }
}

__global__ void __launch_bounds__(1024)
apply_kernel(float* __restrict__ out)
{
    int i = blockIdx.x * 1024 + threadIdx.x;   // grid 2048, one float4 per thread
    int c = (i >> 8) & 127;
    float4 v = ((float4*)out)[i];
    float sc = g_scale[c], sh = g_shift[c];
    v.x = fmaxf(fmaf(v.x, sc, sh), 0.f);
    v.y = fmaxf(fmaf(v.y, sc, sh), 0.f);
    v.z = fmaxf(fmaf(v.z, sc, sh), 0.f);
    v.w = fmaxf(fmaf(v.w, sc, sh), 0.f);
    ((float4*)out)[i] = v;
}

extern "C" void kernel_launch(void* const* d_in, const int* in_sizes, int n_in,
                              void* d_out, int out_size)
{
    const float* x      = (const float*)d_in[0];
    const int*   h      = (const int*)  d_in[1];
    const int*   w      = (const int*)  d_in[2];
    const float* weight = (const float*)d_in[3];
    const float* bias   = (const float*)d_in[4];
    const float* gamma  = (const float*)d_in[5];
    const float* beta   = (const float*)d_in[6];
    float* out = (float*)d_out;

    cudaFuncSetAttribute(build_A, cudaFuncAttributeMaxDynamicSharedMemorySize, 66048);
    cudaFuncSetAttribute(fused_kernel, cudaFuncAttributeMaxDynamicSharedMemorySize, SMEM_TOTAL);

    build_A<<<dim3(4, BB), 512, 66048>>>(x);
    fused_kernel<<<dim3(COUTT / TC, BB), 512, SMEM_TOTAL>>>(h, w, weight, bias, out);
    stats_kernel<<<4, 1024>>>(gamma, beta);
    apply_kernel<<<2048, 1024>>>(out);
}

// round 14
// speedup vs baseline: 1.5936x; 1.0023x over previous
#include <cuda_runtime.h>
#include <cuda_fp16.h>
#include <math.h>
#include <cstdint>

#define BB 64
#define CINN 64
#define COUTT 128
#define NPIX 1024
#define TC 4

// fused SMEM: Ys[9 taps][33 rows][40 cols][4 co] f32 = 190080 B (rows 0..31 data, 4-col zero
// halos; row 32 all-zero). W fp16 (40 rows x 144B) at 190080. red (128 f32) at 195968.
#define ZROW 32
#define SM_W   190080
#define SM_RED 195968
#define SMEM_TOTAL 196480

// A_g: per (b,kstep=16cin) plane of 2048 uint4 in m16n8k16-fp16 A-fragment order.
__device__ uint4 A_g[BB * 4 * 2048];
__device__ float g_psum[COUTT * BB];
__device__ float g_psumsq[COUTT * BB];
__device__ float g_scale[COUTT];
__device__ float g_shift[COUTT];

__device__ __forceinline__ void mma_f16(float* d, const uint32_t* a, const uint32_t* b) {
    asm volatile("mma.sync.aligned.m16n8k16.row.col.f32.f16.f16.f32 "
        "{%0,%1,%2,%3}, {%4,%5,%6,%7}, {%8,%9}, {%0,%1,%2,%3};"
        : "+f"(d[0]), "+f"(d[1]), "+f"(d[2]), "+f"(d[3])
        : "r"(a[0]), "r"(a[1]), "r"(a[2]), "r"(a[3]), "r"(b[0]), "r"(b[1]));
}
__device__ __forceinline__ uint32_t pkh(float a, float b) {
    __half2 h = __floats2half2_rn(a, b);
    return *(uint32_t*)&h;
}
__device__ __forceinline__ int fd3(int a) { return (a + 24) / 3 - 8; }  // floor(a/3), a>=-24

__device__ __forceinline__ float4 f4sel(bool c, float4 b, float4 a) {
    float4 r;
    r.x = c ? b.x : a.x; r.y = c ? b.y : a.y; r.z = c ? b.z : a.z; r.w = c ? b.w : a.w;
    return r;
}
__device__ __forceinline__ float4 f4add(float4 a, float4 b) {
    float4 r;
    r.x = a.x + b.x; r.y = a.y + b.y; r.z = a.z + b.z; r.w = a.w + b.w;
    return r;
}
__device__ __forceinline__ float4 f4max(float4 a, float4 b) {
    float4 r;
    r.x = fmaxf(a.x, b.x); r.y = fmaxf(a.y, b.y); r.z = fmaxf(a.z, b.z); r.w = fmaxf(a.w, b.w);
    return r;
}

// ---- prologue: per (kstep=16cin, b) emit fp16 A plane in m16n8k16 fragment order ----
__global__ void __launch_bounds__(512) build_A(const float* __restrict__ x)
{
    extern __shared__ float Xs[];   // [16][1032]
    const int tid = threadIdx.x, ks = blockIdx.x, b = blockIdx.y;
    const float4* xg = (const float4*)(x + (size_t)b * CINN * NPIX + ks * 16 * NPIX);
#pragma unroll
    for (int j = 0; j < 8; j++) {
        int idx = tid + 512 * j;
        int ci = idx >> 8, px4 = idx & 255;
        *(float4*)(Xs + ci * 1032 + px4 * 4) = xg[idx];
    }
    __syncthreads();
    uint4* pb = A_g + (size_t)(b * 4 + ks) * 2048;
#pragma unroll
    for (int j = 0; j < 4; j++) {
        int idx = tid + 512 * j;
        int l = idx & 31, t = l & 3, g = l >> 2;
        int mtile = idx >> 5;
        int px = mtile * 16 + g;
        uint4 v;
        v.x = pkh(Xs[(2 * t) * 1032 + px],     Xs[(2 * t + 1) * 1032 + px]);
        v.y = pkh(Xs[(2 * t) * 1032 + px + 8], Xs[(2 * t + 1) * 1032 + px + 8]);
        v.z = pkh(Xs[(2 * t + 8) * 1032 + px],     Xs[(2 * t + 9) * 1032 + px]);
        v.w = pkh(Xs[(2 * t + 8) * 1032 + px + 8], Xs[(2 * t + 9) * 1032 + px + 8]);
        pb[idx] = v;
    }
}

__global__ void __launch_bounds__(512, 1)
fused_kernel(const int* __restrict__ hh, const int* __restrict__ wwp,
             const float* __restrict__ weight, const float* __restrict__ bias,
             float* __restrict__ out)
{
    extern __shared__ char smem[];
    float* Y = (float*)smem;
    float4* Y4 = (float4*)smem;
    float* red = (float*)(smem + SM_RED);
    const int tid = threadIdx.x, wid = tid >> 5, l = tid & 31;
    const int b = blockIdx.y, co0 = blockIdx.x * TC;

    // zero column halos: 9 taps x 32 rows x 8 halo-cols x 4 co = 9216 words
    for (int i = tid; i < 9216; i += 512) {
        int tap = i >> 10, rem = i & 1023, r = rem >> 5, k = (rem >> 2) & 7, co = i & 3;
        int col = (k < 4) ? k : (k + 32);
        Y[((tap * 33 + r) * 40 + col) * 4 + co] = 0.f;
    }
    // zero row 32: 9 taps x 160 words
    for (int i = tid; i < 1440; i += 512) {
        int tap = i / 160, rem = i - tap * 160;
        Y[(tap * 33 + ZROW) * 160 + rem] = 0.f;
    }
    // zero W pad rows 36..39 (36 words each)
    for (int i = tid; i < 144; i += 512)
        *(uint32_t*)(smem + SM_W + (36 + i / 36) * 144 + (i % 36) * 4) = 0u;
    // weights fp16: row n = tap*4+c, 144B stride (conflict-free B-frag LDS)
    for (int i = tid; i < TC * CINN * 9; i += 512) {
        int c = i / 576, r = i - c * 576, ci = r / 9, tap = r - ci * 9;
        float w = weight[(co0 + c) * 576 + ci * 9 + tap];
        *(__half*)(smem + SM_W + (tap * 4 + c) * 144 + ci * 2) = __float2half_rn(w);
    }
    __syncthreads();

    float acc[4][5][4];
#pragma unroll
    for (int mt = 0; mt < 4; mt++)
#pragma unroll
        for (int nt = 0; nt < 5; nt++)
#pragma unroll
            for (int k = 0; k < 4; k++) acc[mt][nt][k] = 0.f;

    const int lq = l & 3, ln = l >> 2;
    const int px0 = wid * 64;

    // GEMM with register-double-buffered A fragments (occ-1: reg budget 255)
    uint4 areg[4];
    {
        const uint4* pb0 = A_g + (size_t)(b * 4) * 2048;
#pragma unroll
        for (int mt = 0; mt < 4; mt++) areg[mt] = pb0[(wid * 4 + mt) * 32 + l];
    }
#pragma unroll 1
    for (int ks = 0; ks < 4; ks++) {
        uint4 anext[4];
        if (ks < 3) {
            const uint4* pbn = A_g + (size_t)(b * 4 + ks + 1) * 2048;
#pragma unroll
            for (int mt = 0; mt < 4; mt++) anext[mt] = pbn[(wid * 4 + mt) * 32 + l];
        }
        uint32_t bf[5][2];
#pragma unroll
        for (int nt = 0; nt < 5; nt++) {
            int base = SM_W + (nt * 8 + ln) * 144 + (ks * 16 + 2 * lq) * 2;
            bf[nt][0] = *(uint32_t*)(smem + base);
            bf[nt][1] = *(uint32_t*)(smem + base + 16);
        }
#pragma unroll
        for (int mt = 0; mt < 4; mt++)
#pragma unroll
            for (int nt = 0; nt < 5; nt++)
                mma_f16(acc[mt][nt], (const uint32_t*)&areg[mt], bf[nt]);
        if (ks < 3) {
#pragma unroll
            for (int mt = 0; mt < 4; mt++) areg[mt] = anext[mt];
        }
    }
    __syncthreads();

    // readout into [tap][row][col][co]: c-row n = tap*4+co
#pragma unroll
    for (int mt = 0; mt < 4; mt++)
#pragma unroll
        for (int nt = 0; nt < 5; nt++) {
            int c0 = nt * 8 + 2 * lq;
            if (nt == 4 && lq >= 2) continue;  // c 36..39 unused
            int tap = c0 >> 2, co = c0 & 3;
            int px = px0 + mt * 16 + ln;
            int base = ((tap * 33 + (px >> 5)) * 40 + (px & 31) + 4) * 4 + co;
            Y[base]      = acc[mt][nt][0];
            Y[base + 1]  = acc[mt][nt][1];
            Y[base + 32] = acc[mt][nt][2];  // col +8
            Y[base + 33] = acc[mt][nt][3];
        }
    __syncthreads();

    // ---- combine: float4 over 4 co, padded loads, factorized max, deferred bias ----
    int dh = 96 / hh[b];  if (dh < 1) dh = 1;
    int dw = 96 / wwp[b]; if (dw < 1) dw = 1;
    int rv[3][2]; bool rsel[3][3];
    int dcl0, dch0, dcl2, dch2; bool cdup0, cdup2, csel0[3], csel2[3];
#pragma unroll
    for (int k = 0; k < 3; k++) {
        int d0 = fd3((k - 1) * dh), d1 = fd3(1 + (k - 1) * dh), d2 = fd3(2 + (k - 1) * dh);
        rv[k][0] = d0; rv[k][1] = d2;
        rsel[k][0] = false; rsel[k][1] = (d1 != d0); rsel[k][2] = (d2 != d0);
    }
    {
        int c0 = fd3(-dw), c1 = fd3(1 - dw), c2 = fd3(2 - dw);
        dcl0 = c0; dch0 = c2; cdup0 = (c2 != c0);
        csel0[0] = false; csel0[1] = (c1 != c0); csel0[2] = (c2 != c0);
        int e0 = fd3(dw), e1 = fd3(1 + dw), e2 = fd3(2 + dw);
        dcl2 = e0; dch2 = e2; cdup2 = (e2 != e0);
        csel2[0] = false; csel2[1] = (e1 != e0); csel2[2] = (e2 != e0);
    }
    const bool vneed0 = (rv[0][1] != rv[0][0]);
    const bool vneed2 = (rv[2][1] != rv[2][0]);
    const float4 bias4 = *(const float4*)&bias[co0];
    float4 lsum4 = make_float4(0.f, 0.f, 0.f, 0.f);
    float4 lsq4  = make_float4(0.f, 0.f, 0.f, 0.f);

#pragma unroll
    for (int j = 0; j < 2; j++) {
        int pix = tid + (j << 9), py = pix >> 5, px = pix & 31;
        const int colA0 = 4 + px + dcl0, colB0 = 4 + px + dch0;
        const int colC  = 4 + px;
        const int colA2 = 4 + px + dcl2, colB2 = 4 + px + dch2;

        // center tap-row (ki=1): no bias (deferred past the max)
        float4 RS1[3];
        {
            int r3 = (3 * 33 + py) * 40, r4 = r3 + 1320, r5 = r4 + 1320;
            float4 A0 = Y4[r3 + colA0];
            float4 B0 = cdup0 ? Y4[r3 + colB0] : A0;
            float4 Lc = Y4[r4 + colC];
            float4 A2 = Y4[r5 + colA2];
            float4 B2 = cdup2 ? Y4[r5 + colB2] : A2;
#pragma unroll
            for (int s = 0; s < 3; s++)
                RS1[s] = f4add(Lc,
                          f4add(f4sel(csel0[s], B0, A0), f4sel(csel2[s], B2, A2)));
        }
        float4 RS0[2][3], RS2[2][3];
#pragma unroll
        for (int ki = 0; ki < 3; ki += 2) {
            float4 (*RS)[3] = (ki == 0) ? RS0 : RS2;
            const bool vneed = (ki == 0) ? vneed0 : vneed2;
#pragma unroll
            for (int v = 0; v < 2; v++) {
                if (v == 1 && !vneed) {
#pragma unroll
                    for (int s = 0; s < 3; s++) RS[1][s] = RS[0][s];
                    break;
                }
                int row = py + rv[ki][v];
                int rowsel = ((unsigned)row < 32u) ? row : ZROW;
                int t0 = ((ki * 3) * 33 + rowsel) * 40, t1 = t0 + 1320, t2 = t1 + 1320;
                float4 A0 = Y4[t0 + colA0];
                float4 B0 = cdup0 ? Y4[t0 + colB0] : A0;
                float4 Lc = Y4[t1 + colC];
                float4 A2 = Y4[t2 + colA2];
                float4 B2 = cdup2 ? Y4[t2 + colB2] : A2;
#pragma unroll
                for (int s = 0; s < 3; s++)
                    RS[v][s] = f4add(Lc,
                        f4add(f4sel(csel0[s], B0, A0), f4sel(csel2[s], B2, A2)));
            }
        }
        // mx = bias + max_s( RS1[s] + max_r(v0[r][s] + v2[r][s]) )  -- exact set identity
        float4 mall = make_float4(-INFINITY, -INFINITY, -INFINITY, -INFINITY);
#pragma unroll
        for (int s = 0; s < 3; s++) {
            float4 t0 = f4add(RS0[0][s], RS2[0][s]);   // r=0: rsel[.][0]=false
            float4 t1 = f4add(rsel[0][1] ? RS0[1][s] : RS0[0][s],
                              rsel[2][1] ? RS2[1][s] : RS2[0][s]);
            float4 t2 = f4add(rsel[0][2] ? RS0[1][s] : RS0[0][s],
                              rsel[2][2] ? RS2[1][s] : RS2[0][s]);
            float4 u = f4max(t0, f4max(t1, t2));
            mall = f4max(mall, f4add(u, RS1[s]));
        }
        float4 mx = f4add(bias4, mall);
        float* ob = out + ((size_t)b * COUTT + co0) * NPIX + pix;
        ob[0]        = mx.x;
        ob[NPIX]     = mx.y;
        ob[2 * NPIX] = mx.z;
        ob[3 * NPIX] = mx.w;
        lsum4 = f4add(lsum4, mx);
        lsq4.x += mx.x * mx.x; lsq4.y += mx.y * mx.y;
        lsq4.z += mx.z * mx.z; lsq4.w += mx.w * mx.w;
    }
#pragma unroll
    for (int o = 16; o > 0; o >>= 1) {
        lsum4.x += __shfl_xor_sync(0xFFFFFFFFu, lsum4.x, o);
        lsum4.y += __shfl_xor_sync(0xFFFFFFFFu, lsum4.y, o);
        lsum4.z += __shfl_xor_sync(0xFFFFFFFFu, lsum4.z, o);
        lsum4.w += __shfl_xor_sync(0xFFFFFFFFu, lsum4.w, o);
        lsq4.x  += __shfl_xor_sync(0xFFFFFFFFu, lsq4.x, o);
        lsq4.y  += __shfl_xor_sync(0xFFFFFFFFu, lsq4.y, o);
        lsq4.z  += __shfl_xor_sync(0xFFFFFFFFu, lsq4.z, o);
        lsq4.w  += __shfl_xor_sync(0xFFFFFFFFu, lsq4.w, o);
    }
    __syncthreads();
    if (l == 0) {
        float* rw = red + wid * 8;
        rw[0] = lsum4.x; rw[1] = lsq4.x;
        rw[2] = lsum4.y; rw[3] = lsq4.y;
        rw[4] = lsum4.z; rw[5] = lsq4.z;
        rw[6] = lsum4.w; rw[7] = lsq4.w;
    }
    __syncthreads();
    if (tid < TC) {
        float s = 0.f, q = 0.f;
#pragma unroll
        for (int wdx = 0; wdx < 16; wdx++) {
            s += red[wdx * 8 + tid * 2];
            q += red[wdx * 8 + tid * 2 + 1];
        }
        g_psum[(co0 + tid) * BB + b] = s;
        g_psumsq[(co0 + tid) * BB + b] = q;
    }
}

// warp-per-channel: grid 4 x 1024 threads = 128 warps
__global__ void __launch_bounds__(1024)
stats_kernel(const float* __restrict__ gamma, const float* __restrict__ beta)
{
    int gw = (blockIdx.x * 1024 + threadIdx.x) >> 5;   // channel 0..127
    int l = threadIdx.x & 31;
    float s = g_psum[gw * BB + l] + g_psum[gw * BB + 32 + l];
    float q = g_psumsq[gw * BB + l] + g_psumsq[gw * BB + 32 + l];
#pragma unroll
    for (int o = 16; o > 0; o >>= 1) {
        s += __shfl_xor_sync(0xFFFFFFFFu, s, o);
        q += __shfl_xor_sync(0xFFFFFFFFu, q, o);
    }
    if (l == 0) {
        const float inv = 1.0f / 65536.0f;
        float mean = s * inv, var = q * inv - mean * mean;
        float sc = gamma[gw] * rsqrtf(var + 1e-5f);
        g_scale[gw] = sc;
        g_shift[gw] = beta[gw] - mean * sc;
    }
}

// 256 blocks x 1024 threads, 8 batched float4 per thread (MLP 8)
__global__ void __launch_bounds__(1024)
apply_kernel(float* __restrict__ out)
{
    int t = blockIdx.x * 1024 + threadIdx.x;   // 0..262143
    float4* o = (float4*)out;
    float4 v[8];
#pragma unroll
    for (int j = 0; j < 8; j++) v[j] = o[t + j * 262144];
#pragma unroll
    for (int j = 0; j < 8; j++) {
        int i = t + j * 262144;
        int c = (i >> 8) & 127;
        float sc = g_scale[c], sh = g_shift[c];
        v[j].x = fmaxf(fmaf(v[j].x, sc, sh), 0.f);
        v[j].y = fmaxf(fmaf(v[j].y, sc, sh), 0.f);
        v[j].z = fmaxf(fmaf(v[j].z, sc, sh), 0.f);
        v[j].w = fmaxf(fmaf(v[j].w, sc, sh), 0.f);
        o[i] = v[j];
    }
}

extern "C" void kernel_launch(void* const* d_in, const int* in_sizes, int n_in,
                              void* d_out, int out_size)
{
    const float* x      = (const float*)d_in[0];
    const int*   h      = (const int*)  d_in[1];
    const int*   w      = (const int*)  d_in[2];
    const float* weight = (const float*)d_in[3];
    const float* bias   = (const float*)d_in[4];
    const float* gamma  = (const float*)d_in[5];
    const float* beta   = (const float*)d_in[6];
    float* out = (float*)d_out;

    cudaFuncSetAttribute(build_A, cudaFuncAttributeMaxDynamicSharedMemorySize, 66048);
    cudaFuncSetAttribute(fused_kernel, cudaFuncAttributeMaxDynamicSharedMemorySize, SMEM_TOTAL);

    build_A<<<dim3(4, BB), 512, 66048>>>(x);
    fused_kernel<<<dim3(COUTT / TC, BB), 512, SMEM_TOTAL>>>(h, w, weight, bias, out);
    stats_kernel<<<4, 1024>>>(gamma, beta);
    apply_kernel<<<256, 1024>>>(out);
}